// round 15
// baseline (speedup 1.0000x reference)
#include <cuda_runtime.h>
#include <math.h>

#define T_LEN 2048
#define BATCH 64
#define EMB   100
#define HID   128
#define G3    384   // 3*HID gate rows
#define NS    6     // CRF states

#define KNEG (-1.44269504088896340736f)   // -log2(e)

// ---------------- device scratch (no allocation allowed) ----------------
// unit-major, padded 1 timestep each side (branchless prefetch):
//   g_girz[dir][t][unit] = ( -log2e*(gi_r+bhh_r), -log2e*(gi_z+bhh_z) )
//   g_gin [dir][t][unit] =   gi_n   (plain)
__device__ float2 g_girz[2][T_LEN + 2][HID];
__device__ float  g_gin [2][T_LEN + 2][HID];
__device__ float g_hout[2][T_LEN][HID];
__device__ __align__(16) float g_logits[T_LEN * NS];

// ---------------- f32x2 helpers (packed dual-FP32 FMA, sm_100+) ---------
__device__ __forceinline__ unsigned long long ffma2(unsigned long long a,
                                                    unsigned long long b,
                                                    unsigned long long c) {
    unsigned long long d;
    asm("fma.rn.f32x2 %0, %1, %2, %3;" : "=l"(d) : "l"(a), "l"(b), "l"(c));
    return d;
}
__device__ __forceinline__ unsigned long long fadd2(unsigned long long a,
                                                    unsigned long long b) {
    unsigned long long d;
    asm("add.rn.f32x2 %0, %1, %2;" : "=l"(d) : "l"(a), "l"(b));
    return d;
}
__device__ __forceinline__ unsigned long long pack2(float lo, float hi) {
    unsigned long long d;
    asm("mov.b64 %0, {%1, %2};" : "=l"(d) : "f"(lo), "f"(hi));
    return d;
}
__device__ __forceinline__ float2 unpack2(unsigned long long u) {
    float2 r;
    asm("mov.b64 {%0, %1}, %2;" : "=f"(r.x), "=f"(r.y) : "l"(u));
    return r;
}
__device__ __forceinline__ float fex2(float x) {
    float r; asm("ex2.approx.f32 %0, %1;" : "=f"(r) : "f"(x)); return r;
}
__device__ __forceinline__ float frcp(float x) {
    float r; asm("rcp.approx.f32 %0, %1;" : "=f"(r) : "f"(x)); return r;
}
__device__ __forceinline__ float ftanh(float x) {
    float r; asm("tanh.approx.f32 %0, %1;" : "=f"(r) : "f"(x)); return r;
}

// ================= Kernel 1: gi precompute (split rz/n layout) ============
__global__ void __launch_bounds__(G3) gi_kernel(
    const int* __restrict__ sentence, const float* __restrict__ emb,
    const float* __restrict__ Wf_ih, const float* __restrict__ bf_ih,
    const float* __restrict__ Wb_ih, const float* __restrict__ bb_ih,
    const float* __restrict__ bf_hh, const float* __restrict__ bb_hh)
{
    const int dir = blockIdx.y;
    const int t0  = blockIdx.x * 8;
    __shared__ float x_s[8][EMB];

    for (int i = threadIdx.x; i < 8 * EMB; i += G3) {
        int tt = i / EMB, e = i % EMB;
        int tok = sentence[63 * T_LEN + t0 + tt];
        x_s[tt][e] = emb[tok * EMB + e];
    }
    __syncthreads();

    const float* W   = dir ? Wb_ih : Wf_ih;
    const float* b   = dir ? bb_ih : bf_ih;
    const float* bhh = dir ? bb_hh : bf_hh;
    const int j    = threadIdx.x;      // gate row 0..383
    const int gate = j >> 7;           // 0=r, 1=z, 2=n
    const int unit = j & 127;

    float bj = b[j] + ((gate < 2) ? bhh[j] : 0.0f);
    const float scale = (gate < 2) ? KNEG : 1.0f;
    float acc[8];
#pragma unroll
    for (int q = 0; q < 8; q++) acc[q] = bj;
    const float* Wr = W + j * EMB;
#pragma unroll
    for (int e = 0; e < EMB; e++) {
        float w = __ldg(Wr + e);
#pragma unroll
        for (int q = 0; q < 8; q++) acc[q] += w * x_s[q][e];
    }
#pragma unroll
    for (int q = 0; q < 8; q++) {
        float v = acc[q] * scale;
        if (gate == 0)      g_girz[dir][t0 + q + 1][unit].x = v;
        else if (gate == 1) g_girz[dir][t0 + q + 1][unit].y = v;
        else                g_gin [dir][t0 + q + 1][unit]   = v;
    }
}

// ================= Kernel 2: GRU recurrence (R13 body, 2-LDG prefetch) ====
// grid 2, block 256. Thread pair (2u,2u+1) owns unit u; r,z,n half-dots over
// its 64-slice of h, shfl_xor(1) combine, thread-local tail, ONE barrier.
__global__ void __launch_bounds__(256, 1) gru_kernel(
    const float* __restrict__ Wf_hh, const float* __restrict__ bf_hh,
    const float* __restrict__ Wb_hh, const float* __restrict__ bb_hh,
    const float* __restrict__ h0)
{
    const int dir  = blockIdx.x;
    const int tid  = threadIdx.x;
    const int unit = tid >> 1;       // 0..127
    const int half = tid & 1;        // which 64-slice of h

    __shared__ __align__(16) float h_s[2][136];

    const float* Whh = dir ? Wb_hh : Wf_hh;
    const float* bhh = dir ? bb_hh : bf_hh;

    unsigned long long wr[32], wz[32], wn[32];
    {
        const unsigned long long* Pr = reinterpret_cast<const unsigned long long*>(
            Whh + unit * HID + half * 64);
        const unsigned long long* Pz = reinterpret_cast<const unsigned long long*>(
            Whh + (HID + unit) * HID + half * 64);
        const unsigned long long* Pn = reinterpret_cast<const unsigned long long*>(
            Whh + (2 * HID + unit) * HID + half * 64);
#pragma unroll
        for (int k = 0; k < 32; k++) {
            wr[k] = __ldg(Pr + k);
            wz[k] = __ldg(Pz + k);
            wn[k] = __ldg(Pn + k);
        }
    }
    const float bias_n = bhh[2 * HID + unit];
    const unsigned long long an_init =
        (half == 0) ? pack2(bias_n, 0.0f) : 0ull;

    float hold = h0[dir * (BATCH * HID) + 63 * HID + unit];
    const int wslot = unit + ((unit >> 6) << 3);
    if (half == 0) h_s[0][wslot] = hold;
    __syncthreads();

    const int tstep = dir ? -1 : 1;
    int t0q = dir ? (T_LEN - 1) : 0;
    const float2* grzp = &g_girz[dir][1][0] + t0q * HID + unit;
    const float*  gnp  = &g_gin [dir][1][0] + t0q * HID + unit;
    float*        houp = &g_hout[dir][0][0] + t0q * HID + unit;
    const int gstep = tstep * HID;
    const int hstep = tstep * HID;

    float2 grz = __ldg(grzp);          // (gr, gz)  prescaled
    float  gn  = __ldg(gnp);           // plain
    grzp += gstep; gnp += gstep;

    const int hoff = half ? 72 : 0;

#pragma unroll 4
    for (int s = 0; s < T_LEN; s++) {
        const int p = s & 1;
        float2 grz2 = __ldg(grzp);     // prefetch next step (2 LDGs total)
        float  gn2  = __ldg(gnp);
        grzp += gstep; gnp += gstep;

        unsigned long long ar0 = 0ull, ar1 = 0ull;
        unsigned long long az0 = 0ull, az1 = 0ull;
        unsigned long long an0 = an_init, an1 = 0ull;
        const ulonglong2* h2 =
            reinterpret_cast<const ulonglong2*>(&h_s[p][hoff]);
#pragma unroll
        for (int q = 0; q < 16; q++) {
            ulonglong2 v = h2[q];
            ar0 = ffma2(wr[2 * q], v.x, ar0);
            ar1 = ffma2(wr[2 * q + 1], v.y, ar1);
            az0 = ffma2(wz[2 * q], v.x, az0);
            az1 = ffma2(wz[2 * q + 1], v.y, az1);
            an0 = ffma2(wn[2 * q], v.x, an0);
            an1 = ffma2(wn[2 * q + 1], v.y, an1);
        }
        // r drains first: sr chain hides under z/n drains
        float2 fr = unpack2(fadd2(ar0, ar1));
        float pr = fr.x + fr.y;
        float dr = pr + __shfl_xor_sync(0xFFFFFFFFu, pr, 1);
        float2 fz = unpack2(fadd2(az0, az1));
        float pz = fz.x + fz.y;
        float dz = pz + __shfl_xor_sync(0xFFFFFFFFu, pz, 1);
        float2 fn = unpack2(fadd2(an0, an1));
        float pn = fn.x + fn.y;
        float dn = pn + __shfl_xor_sync(0xFFFFFFFFu, pn, 1);

        float sr = frcp(1.0f + fex2(fmaf(KNEG, dr, grz.x)));  // sigmoid
        float sz = frcp(1.0f + fex2(fmaf(KNEG, dz, grz.y)));  // sigmoid
        float nn = ftanh(fmaf(sr, dn, gn));                   // MUFU.TANH
        float hnew = fmaf(sz, hold - nn, nn);                 // (1-z)n + z h

        if (half == 0) h_s[p ^ 1][wslot] = hnew;              // publish
        else           *houp = hnew;                          // stream out
        __syncthreads();                                      // only barrier

        hold = hnew;
        grz = grz2; gn = gn2;
        houp += hstep;
    }
}

// ============ Kernel 3: output projection + softmax, 4 t per block ========
__global__ void __launch_bounds__(192) proj_kernel(
    const float* __restrict__ W_out, const float* __restrict__ b_out)
{
    const int wid  = threadIdx.x >> 5;   // state 0..5
    const int lane = threadIdx.x & 31;
    __shared__ float lg_s[NS];

    const float* Wr = W_out + wid * (2 * HID);

#pragma unroll
    for (int q = 0; q < 4; q++) {
        const int t = blockIdx.x * 4 + q;

        float acc = 0.0f;
#pragma unroll
        for (int i = lane; i < 2 * HID; i += 32) {
            float c = (i < HID) ? g_hout[0][t][i] : g_hout[1][t][i - HID];
            acc += c * __ldg(Wr + i);
        }
#pragma unroll
        for (int off = 16; off; off >>= 1)
            acc += __shfl_xor_sync(0xFFFFFFFFu, acc, off);
        if (lane == 0) lg_s[wid] = acc + b_out[wid];
        __syncthreads();

        if (threadIdx.x == 0) {
            float m = lg_s[0];
#pragma unroll
            for (int i = 1; i < NS; i++) m = fmaxf(m, lg_s[i]);
            float e[NS];
            float sum = 0.0f;
#pragma unroll
            for (int i = 0; i < NS; i++) { e[i] = expf(lg_s[i] - m); sum += e[i]; }
            float inv = 1.0f / sum;
#pragma unroll
            for (int i = 0; i < NS; i++) g_logits[t * NS + i] = e[i] * inv;
        }
        __syncthreads();
    }
}

// ================= Kernel 4: Viterbi (1 warp) — round-5 proven version ====
__global__ void viterbi_kernel(const float* __restrict__ transitions,
                               float* __restrict__ out, int out_size)
{
    extern __shared__ char sm[];
    float*         lg_sh = (float*)sm;                        // T*6 floats
    unsigned char* bp8   = (unsigned char*)(sm + T_LEN * NS * 4); // (T-1)*8
    const int lane = threadIdx.x;

    {   // stage logits into SMEM
        const float4* src = (const float4*)g_logits;
        float4*       dst = (float4*)lg_sh;
        for (int i = lane; i < T_LEN * NS / 4; i += 32) dst[i] = src[i];
    }
    __syncwarp();

    float Tc[NS];
#pragma unroll
    for (int i = 0; i < NS; i++)
        Tc[i] = (lane < NS) ? transitions[i * NS + lane] : 0.0f;

    const int l6 = (lane < NS) ? lane : 0;
    float tr = (lane < NS) ? lg_sh[lane] : -1e30f;

    for (int t = 1; t < T_LEN; t++) {
        float lgv = lg_sh[t * NS + l6];
        float v0 = __shfl_sync(0xFFFFFFFFu, tr, 0) + Tc[0];
        float v1 = __shfl_sync(0xFFFFFFFFu, tr, 1) + Tc[1];
        float v2 = __shfl_sync(0xFFFFFFFFu, tr, 2) + Tc[2];
        float v3 = __shfl_sync(0xFFFFFFFFu, tr, 3) + Tc[3];
        float v4 = __shfl_sync(0xFFFFFFFFu, tr, 4) + Tc[4];
        float v5 = __shfl_sync(0xFFFFFFFFu, tr, 5) + Tc[5];
        float m01 = fmaxf(v0, v1);  int i01 = (v0 >= v1) ? 0 : 1;
        float m23 = fmaxf(v2, v3);  int i23 = (v2 >= v3) ? 2 : 3;
        float m45 = fmaxf(v4, v5);  int i45 = (v4 >= v5) ? 4 : 5;
        float m03 = fmaxf(m01, m23); int i03 = (m01 >= m23) ? i01 : i23;
        float m   = fmaxf(m03, m45); int bi  = (m03 >= m45) ? i03 : i45;
        if (lane < NS) {
            tr = lgv + m;
            bp8[(t - 1) * 8 + lane] = (unsigned char)bi;
        }
    }

    float f0 = __shfl_sync(0xFFFFFFFFu, tr, 0);
    float f1 = __shfl_sync(0xFFFFFFFFu, tr, 1);
    float f2 = __shfl_sync(0xFFFFFFFFu, tr, 2);
    float f3 = __shfl_sync(0xFFFFFFFFu, tr, 3);
    float f4 = __shfl_sync(0xFFFFFFFFu, tr, 4);
    float f5 = __shfl_sync(0xFFFFFFFFu, tr, 5);
    float n01 = fmaxf(f0, f1);  int k01 = (f0 >= f1) ? 0 : 1;
    float n23 = fmaxf(f2, f3);  int k23 = (f2 >= f3) ? 2 : 3;
    float n45 = fmaxf(f4, f5);  int k45 = (f4 >= f5) ? 4 : 5;
    float n03 = fmaxf(n01, n23); int k03 = (n01 >= n23) ? k01 : k23;
    float score = fmaxf(n03, n45); int last = (n03 >= n45) ? k03 : k45;
    if (lane == 0) out[0] = score;
    __syncwarp();

    // ---- parallel backtrack: 32 chunks x 64 steps, nibble maps ----
    const unsigned int IDENT = 0x00543210u;
    unsigned int mp_loc[64];
#pragma unroll
    for (int s2 = 0; s2 < 64; s2++) {
        int k = lane * 64 + s2;
        if (k <= T_LEN - 2) {
            unsigned long long f8 =
                *reinterpret_cast<const unsigned long long*>(&bp8[k * 8]);
            unsigned int lo = (unsigned int)f8;
            unsigned int hi = (unsigned int)(f8 >> 32);
            mp_loc[s2] = (lo & 0xFu) | ((lo >> 4) & 0xF0u) |
                         ((lo >> 8) & 0xF00u) | ((lo >> 12) & 0xF000u) |
                         ((hi & 0xFu) << 16) | (((hi >> 8) & 0xFu) << 20);
        } else {
            mp_loc[s2] = IDENT;
        }
    }
    unsigned int M = IDENT;
#pragma unroll
    for (int s2 = 63; s2 >= 0; s2--) {
        unsigned int f = mp_loc[s2];
        unsigned int Mn = 0;
#pragma unroll
        for (int jq = 0; jq < 6; jq++) {
            unsigned int y = (M >> (4 * jq)) & 15u;
            Mn |= ((f >> (4 * y)) & 15u) << (4 * jq);
        }
        M = Mn;
    }
    unsigned int S = M;
#pragma unroll
    for (int d = 1; d < 32; d <<= 1) {
        unsigned int other = __shfl_down_sync(0xFFFFFFFFu, S, d);
        if (lane + d < 32) {
            unsigned int Sn = 0;
#pragma unroll
            for (int jq = 0; jq < 6; jq++) {
                unsigned int y = (other >> (4 * jq)) & 15u;
                Sn |= ((S >> (4 * y)) & 15u) << (4 * jq);
            }
            S = Sn;
        }
    }
    unsigned int Snext = __shfl_down_sync(0xFFFFFFFFu, S, 1);
    int cur = (lane == 31) ? last : (int)((Snext >> (4 * last)) & 15u);
#pragma unroll
    for (int s2 = 63; s2 >= 0; s2--) {
        int k = lane * 64 + s2;
        if (k <= T_LEN - 2) {
            cur = (int)((mp_loc[s2] >> (4 * cur)) & 15u);
            out[1 + k] = (float)cur;
        }
    }
    if (lane == 31) out[1 + T_LEN - 1] = (float)last;
    for (int i = T_LEN + 1 + lane; i < out_size; i += 32) out[i] = 0.0f;
}

// ============================ launch =======================================
extern "C" void kernel_launch(void* const* d_in, const int* in_sizes, int n_in,
                              void* d_out, int out_size) {
    const int*   sentence    = (const int*)d_in[0];
    const float* emb         = (const float*)d_in[1];
    const float* h0          = (const float*)d_in[2];
    const float* Wf_ih       = (const float*)d_in[3];
    const float* Wf_hh       = (const float*)d_in[4];
    const float* bf_ih       = (const float*)d_in[5];
    const float* bf_hh       = (const float*)d_in[6];
    const float* Wb_ih       = (const float*)d_in[7];
    const float* Wb_hh       = (const float*)d_in[8];
    const float* bb_ih       = (const float*)d_in[9];
    const float* bb_hh       = (const float*)d_in[10];
    const float* W_out       = (const float*)d_in[11];
    const float* b_out       = (const float*)d_in[12];
    const float* transitions = (const float*)d_in[13];
    float*       out         = (float*)d_out;

    const int vit_smem = T_LEN * NS * 4 + (T_LEN - 1) * 8;  // 65528 B
    cudaFuncSetAttribute(viterbi_kernel,
                         cudaFuncAttributeMaxDynamicSharedMemorySize, vit_smem);

    gi_kernel<<<dim3(T_LEN / 8, 2), G3>>>(sentence, emb, Wf_ih, bf_ih,
                                          Wb_ih, bb_ih, bf_hh, bb_hh);
    gru_kernel<<<2, 256>>>(Wf_hh, bf_hh, Wb_hh, bb_hh, h0);
    proj_kernel<<<T_LEN / 4, 192>>>(W_out, b_out);
    viterbi_kernel<<<1, 32, vit_smem>>>(transitions, out, out_size);
}

// round 16
// speedup vs baseline: 1.1988x; 1.1988x over previous
#include <cuda_runtime.h>
#include <math.h>

#define T_LEN 2048
#define BATCH 64
#define EMB   100
#define HID   128
#define G3    384   // 3*HID gate rows
#define NS    6     // CRF states

#define KNEG (-1.44269504088896340736f)   // -log2(e)

// ---------------- device scratch (no allocation allowed) ----------------
// g_gi padded by 1 timestep each side -> branchless prefetch in the GRU loop
// r,z rows: -log2e * (x@Wih^T + bih + bhh); n rows: plain x@Wih^T + bih
__device__ float g_gi[2][T_LEN + 2][G3];
__device__ float g_hout[2][T_LEN][HID];
__device__ __align__(16) float g_logits[T_LEN * NS];

// ---------------- f32x2 helpers (packed dual-FP32 FMA, sm_100+) ---------
__device__ __forceinline__ unsigned long long ffma2(unsigned long long a,
                                                    unsigned long long b,
                                                    unsigned long long c) {
    unsigned long long d;
    asm("fma.rn.f32x2 %0, %1, %2, %3;" : "=l"(d) : "l"(a), "l"(b), "l"(c));
    return d;
}
__device__ __forceinline__ unsigned long long fadd2(unsigned long long a,
                                                    unsigned long long b) {
    unsigned long long d;
    asm("add.rn.f32x2 %0, %1, %2;" : "=l"(d) : "l"(a), "l"(b));
    return d;
}
__device__ __forceinline__ unsigned long long pack2(float lo, float hi) {
    unsigned long long d;
    asm("mov.b64 %0, {%1, %2};" : "=l"(d) : "f"(lo), "f"(hi));
    return d;
}
__device__ __forceinline__ float2 unpack2(unsigned long long u) {
    float2 r;
    asm("mov.b64 {%0, %1}, %2;" : "=f"(r.x), "=f"(r.y) : "l"(u));
    return r;
}
__device__ __forceinline__ float fex2(float x) {
    float r; asm("ex2.approx.f32 %0, %1;" : "=f"(r) : "f"(x)); return r;
}
__device__ __forceinline__ float frcp(float x) {
    float r; asm("rcp.approx.f32 %0, %1;" : "=f"(r) : "f"(x)); return r;
}
__device__ __forceinline__ float ftanh(float x) {
    float r; asm("tanh.approx.f32 %0, %1;" : "=f"(r) : "f"(x)); return r;
}

// ================= Kernel 1: gi precompute ================================
// r,z rows: -log2e*(x@Wih^T + bih + bhh);  n rows: x@Wih^T + bih (plain)
__global__ void __launch_bounds__(G3) gi_kernel(
    const int* __restrict__ sentence, const float* __restrict__ emb,
    const float* __restrict__ Wf_ih, const float* __restrict__ bf_ih,
    const float* __restrict__ Wb_ih, const float* __restrict__ bb_ih,
    const float* __restrict__ bf_hh, const float* __restrict__ bb_hh)
{
    const int dir = blockIdx.y;
    const int t0  = blockIdx.x * 8;
    __shared__ float x_s[8][EMB];

    for (int i = threadIdx.x; i < 8 * EMB; i += G3) {
        int tt = i / EMB, e = i % EMB;
        int tok = sentence[63 * T_LEN + t0 + tt];
        x_s[tt][e] = emb[tok * EMB + e];
    }
    __syncthreads();

    const float* W   = dir ? Wb_ih : Wf_ih;
    const float* b   = dir ? bb_ih : bf_ih;
    const float* bhh = dir ? bb_hh : bf_hh;
    const int j = threadIdx.x;

    float bj = b[j] + ((j < 2 * HID) ? bhh[j] : 0.0f);
    const float scale = (j < 2 * HID) ? KNEG : 1.0f;
    float acc[8];
#pragma unroll
    for (int q = 0; q < 8; q++) acc[q] = bj;
    const float* Wr = W + j * EMB;
#pragma unroll
    for (int e = 0; e < EMB; e++) {
        float w = __ldg(Wr + e);
#pragma unroll
        for (int q = 0; q < 8; q++) acc[q] += w * x_s[q][e];
    }
#pragma unroll
    for (int q = 0; q < 8; q++) g_gi[dir][t0 + q + 1][j] = acc[q] * scale;
}

// ================= Kernel 2: GRU recurrence (round-10 proven) =============
// grid 2, block 256. Thread pair (2u,2u+1) owns unit u; r,z,n half-dots over
// its 64-slice of h, shfl_xor(1) combine, thread-local tail, ONE barrier.
// n gate via single MUFU.TANH.
__global__ void __launch_bounds__(256, 1) gru_kernel(
    const float* __restrict__ Wf_hh, const float* __restrict__ bf_hh,
    const float* __restrict__ Wb_hh, const float* __restrict__ bb_hh,
    const float* __restrict__ h0)
{
    const int dir  = blockIdx.x;
    const int tid  = threadIdx.x;
    const int unit = tid >> 1;       // 0..127
    const int half = tid & 1;        // which 64-slice of h

    __shared__ __align__(16) float h_s[2][136];

    const float* Whh = dir ? Wb_hh : Wf_hh;
    const float* bhh = dir ? bb_hh : bf_hh;

    unsigned long long wr[32], wz[32], wn[32];
    {
        const unsigned long long* Pr = reinterpret_cast<const unsigned long long*>(
            Whh + unit * HID + half * 64);
        const unsigned long long* Pz = reinterpret_cast<const unsigned long long*>(
            Whh + (HID + unit) * HID + half * 64);
        const unsigned long long* Pn = reinterpret_cast<const unsigned long long*>(
            Whh + (2 * HID + unit) * HID + half * 64);
#pragma unroll
        for (int k = 0; k < 32; k++) {
            wr[k] = __ldg(Pr + k);
            wz[k] = __ldg(Pz + k);
            wn[k] = __ldg(Pn + k);
        }
    }
    const float bias_n = bhh[2 * HID + unit];
    const unsigned long long an_init =
        (half == 0) ? pack2(bias_n, 0.0f) : 0ull;

    float hold = h0[dir * (BATCH * HID) + 63 * HID + unit];
    const int wslot = unit + ((unit >> 6) << 3);
    if (half == 0) h_s[0][wslot] = hold;
    __syncthreads();

    const int tstep = dir ? -1 : 1;
    int t0q = dir ? (T_LEN - 1) : 0;
    const float* gip  = &g_gi[dir][1][0] + t0q * G3 + unit;
    float*       houp = &g_hout[dir][0][0] + t0q * HID + unit;
    const int gstep = tstep * G3;
    const int hstep = tstep * HID;

    float gr = __ldg(gip);              // -log2e prescaled
    float gz = __ldg(gip + HID);        // -log2e prescaled
    float gn = __ldg(gip + 2 * HID);    // plain
    gip += gstep;

    const int hoff = half ? 72 : 0;

#pragma unroll 4
    for (int s = 0; s < T_LEN; s++) {
        const int p = s & 1;
        float gr2 = __ldg(gip);
        float gz2 = __ldg(gip + HID);
        float gn2 = __ldg(gip + 2 * HID);
        gip += gstep;

        unsigned long long ar0 = 0ull, ar1 = 0ull;
        unsigned long long az0 = 0ull, az1 = 0ull;
        unsigned long long an0 = an_init, an1 = 0ull;
        const ulonglong2* h2 =
            reinterpret_cast<const ulonglong2*>(&h_s[p][hoff]);
#pragma unroll
        for (int q = 0; q < 16; q++) {
            ulonglong2 v = h2[q];
            ar0 = ffma2(wr[2 * q], v.x, ar0);
            ar1 = ffma2(wr[2 * q + 1], v.y, ar1);
            az0 = ffma2(wz[2 * q], v.x, az0);
            az1 = ffma2(wz[2 * q + 1], v.y, az1);
            an0 = ffma2(wn[2 * q], v.x, an0);
            an1 = ffma2(wn[2 * q + 1], v.y, an1);
        }
        // r drains first: sr chain hides under z/n drains
        float2 fr = unpack2(fadd2(ar0, ar1));
        float pr = fr.x + fr.y;
        float dr = pr + __shfl_xor_sync(0xFFFFFFFFu, pr, 1);
        float2 fz = unpack2(fadd2(az0, az1));
        float pz = fz.x + fz.y;
        float dz = pz + __shfl_xor_sync(0xFFFFFFFFu, pz, 1);
        float2 fn = unpack2(fadd2(an0, an1));
        float pn = fn.x + fn.y;
        float dn = pn + __shfl_xor_sync(0xFFFFFFFFu, pn, 1);

        float sr = frcp(1.0f + fex2(fmaf(KNEG, dr, gr)));   // sigmoid
        float sz = frcp(1.0f + fex2(fmaf(KNEG, dz, gz)));   // sigmoid
        float nn = ftanh(fmaf(sr, dn, gn));                 // MUFU.TANH
        float hnew = fmaf(sz, hold - nn, nn);               // (1-z)n + z h

        if (half == 0) h_s[p ^ 1][wslot] = hnew;            // publish
        else           *houp = hnew;                        // stream out
        __syncthreads();                                    // only barrier

        hold = hnew;
        gr = gr2; gz = gz2; gn = gn2;
        houp += hstep;
    }
}

// ============ Kernel 3: output projection + softmax, 4 t per block ========
__global__ void __launch_bounds__(192) proj_kernel(
    const float* __restrict__ W_out, const float* __restrict__ b_out)
{
    const int wid  = threadIdx.x >> 5;   // state 0..5
    const int lane = threadIdx.x & 31;
    __shared__ float lg_s[NS];

    const float* Wr = W_out + wid * (2 * HID);

#pragma unroll
    for (int q = 0; q < 4; q++) {
        const int t = blockIdx.x * 4 + q;

        float acc = 0.0f;
#pragma unroll
        for (int i = lane; i < 2 * HID; i += 32) {
            float c = (i < HID) ? g_hout[0][t][i] : g_hout[1][t][i - HID];
            acc += c * __ldg(Wr + i);
        }
#pragma unroll
        for (int off = 16; off; off >>= 1)
            acc += __shfl_xor_sync(0xFFFFFFFFu, acc, off);
        if (lane == 0) lg_s[wid] = acc + b_out[wid];
        __syncthreads();

        if (threadIdx.x == 0) {
            float m = lg_s[0];
#pragma unroll
            for (int i = 1; i < NS; i++) m = fmaxf(m, lg_s[i]);
            float e[NS];
            float sum = 0.0f;
#pragma unroll
            for (int i = 0; i < NS; i++) { e[i] = expf(lg_s[i] - m); sum += e[i]; }
            float inv = 1.0f / sum;
#pragma unroll
            for (int i = 0; i < NS; i++) g_logits[t * NS + i] = e[i] * inv;
        }
        __syncthreads();
    }
}

// ================= Kernel 4: Viterbi (1 warp) — round-5 proven version ====
__global__ void viterbi_kernel(const float* __restrict__ transitions,
                               float* __restrict__ out, int out_size)
{
    extern __shared__ char sm[];
    float*         lg_sh = (float*)sm;                        // T*6 floats
    unsigned char* bp8   = (unsigned char*)(sm + T_LEN * NS * 4); // (T-1)*8
    const int lane = threadIdx.x;

    {   // stage logits into SMEM
        const float4* src = (const float4*)g_logits;
        float4*       dst = (float4*)lg_sh;
        for (int i = lane; i < T_LEN * NS / 4; i += 32) dst[i] = src[i];
    }
    __syncwarp();

    float Tc[NS];
#pragma unroll
    for (int i = 0; i < NS; i++)
        Tc[i] = (lane < NS) ? transitions[i * NS + lane] : 0.0f;

    const int l6 = (lane < NS) ? lane : 0;
    float tr = (lane < NS) ? lg_sh[lane] : -1e30f;

    for (int t = 1; t < T_LEN; t++) {
        float lgv = lg_sh[t * NS + l6];
        float v0 = __shfl_sync(0xFFFFFFFFu, tr, 0) + Tc[0];
        float v1 = __shfl_sync(0xFFFFFFFFu, tr, 1) + Tc[1];
        float v2 = __shfl_sync(0xFFFFFFFFu, tr, 2) + Tc[2];
        float v3 = __shfl_sync(0xFFFFFFFFu, tr, 3) + Tc[3];
        float v4 = __shfl_sync(0xFFFFFFFFu, tr, 4) + Tc[4];
        float v5 = __shfl_sync(0xFFFFFFFFu, tr, 5) + Tc[5];
        float m01 = fmaxf(v0, v1);  int i01 = (v0 >= v1) ? 0 : 1;
        float m23 = fmaxf(v2, v3);  int i23 = (v2 >= v3) ? 2 : 3;
        float m45 = fmaxf(v4, v5);  int i45 = (v4 >= v5) ? 4 : 5;
        float m03 = fmaxf(m01, m23); int i03 = (m01 >= m23) ? i01 : i23;
        float m   = fmaxf(m03, m45); int bi  = (m03 >= m45) ? i03 : i45;
        if (lane < NS) {
            tr = lgv + m;
            bp8[(t - 1) * 8 + lane] = (unsigned char)bi;
        }
    }

    float f0 = __shfl_sync(0xFFFFFFFFu, tr, 0);
    float f1 = __shfl_sync(0xFFFFFFFFu, tr, 1);
    float f2 = __shfl_sync(0xFFFFFFFFu, tr, 2);
    float f3 = __shfl_sync(0xFFFFFFFFu, tr, 3);
    float f4 = __shfl_sync(0xFFFFFFFFu, tr, 4);
    float f5 = __shfl_sync(0xFFFFFFFFu, tr, 5);
    float n01 = fmaxf(f0, f1);  int k01 = (f0 >= f1) ? 0 : 1;
    float n23 = fmaxf(f2, f3);  int k23 = (f2 >= f3) ? 2 : 3;
    float n45 = fmaxf(f4, f5);  int k45 = (f4 >= f5) ? 4 : 5;
    float n03 = fmaxf(n01, n23); int k03 = (n01 >= n23) ? k01 : k23;
    float score = fmaxf(n03, n45); int last = (n03 >= n45) ? k03 : k45;
    if (lane == 0) out[0] = score;
    __syncwarp();

    // ---- parallel backtrack: 32 chunks x 64 steps, nibble maps ----
    const unsigned int IDENT = 0x00543210u;
    unsigned int mp_loc[64];
#pragma unroll
    for (int s2 = 0; s2 < 64; s2++) {
        int k = lane * 64 + s2;
        if (k <= T_LEN - 2) {
            unsigned long long f8 =
                *reinterpret_cast<const unsigned long long*>(&bp8[k * 8]);
            unsigned int lo = (unsigned int)f8;
            unsigned int hi = (unsigned int)(f8 >> 32);
            mp_loc[s2] = (lo & 0xFu) | ((lo >> 4) & 0xF0u) |
                         ((lo >> 8) & 0xF00u) | ((lo >> 12) & 0xF000u) |
                         ((hi & 0xFu) << 16) | (((hi >> 8) & 0xFu) << 20);
        } else {
            mp_loc[s2] = IDENT;
        }
    }
    unsigned int M = IDENT;
#pragma unroll
    for (int s2 = 63; s2 >= 0; s2--) {
        unsigned int f = mp_loc[s2];
        unsigned int Mn = 0;
#pragma unroll
        for (int jq = 0; jq < 6; jq++) {
            unsigned int y = (M >> (4 * jq)) & 15u;
            Mn |= ((f >> (4 * y)) & 15u) << (4 * jq);
        }
        M = Mn;
    }
    unsigned int S = M;
#pragma unroll
    for (int d = 1; d < 32; d <<= 1) {
        unsigned int other = __shfl_down_sync(0xFFFFFFFFu, S, d);
        if (lane + d < 32) {
            unsigned int Sn = 0;
#pragma unroll
            for (int jq = 0; jq < 6; jq++) {
                unsigned int y = (other >> (4 * jq)) & 15u;
                Sn |= ((S >> (4 * y)) & 15u) << (4 * jq);
            }
            S = Sn;
        }
    }
    unsigned int Snext = __shfl_down_sync(0xFFFFFFFFu, S, 1);
    int cur = (lane == 31) ? last : (int)((Snext >> (4 * last)) & 15u);
#pragma unroll
    for (int s2 = 63; s2 >= 0; s2--) {
        int k = lane * 64 + s2;
        if (k <= T_LEN - 2) {
            cur = (int)((mp_loc[s2] >> (4 * cur)) & 15u);
            out[1 + k] = (float)cur;
        }
    }
    if (lane == 31) out[1 + T_LEN - 1] = (float)last;
    for (int i = T_LEN + 1 + lane; i < out_size; i += 32) out[i] = 0.0f;
}

// ============================ launch =======================================
extern "C" void kernel_launch(void* const* d_in, const int* in_sizes, int n_in,
                              void* d_out, int out_size) {
    const int*   sentence    = (const int*)d_in[0];
    const float* emb         = (const float*)d_in[1];
    const float* h0          = (const float*)d_in[2];
    const float* Wf_ih       = (const float*)d_in[3];
    const float* Wf_hh       = (const float*)d_in[4];
    const float* bf_ih       = (const float*)d_in[5];
    const float* bf_hh       = (const float*)d_in[6];
    const float* Wb_ih       = (const float*)d_in[7];
    const float* Wb_hh       = (const float*)d_in[8];
    const float* bb_ih       = (const float*)d_in[9];
    const float* bb_hh       = (const float*)d_in[10];
    const float* W_out       = (const float*)d_in[11];
    const float* b_out       = (const float*)d_in[12];
    const float* transitions = (const float*)d_in[13];
    float*       out         = (float*)d_out;

    const int vit_smem = T_LEN * NS * 4 + (T_LEN - 1) * 8;  // 65528 B
    cudaFuncSetAttribute(viterbi_kernel,
                         cudaFuncAttributeMaxDynamicSharedMemorySize, vit_smem);

    gi_kernel<<<dim3(T_LEN / 8, 2), G3>>>(sentence, emb, Wf_ih, bf_ih,
                                          Wb_ih, bb_ih, bf_hh, bb_hh);
    gru_kernel<<<2, 256>>>(Wf_hh, bf_hh, Wb_hh, bb_hh, h0);
    proj_kernel<<<T_LEN / 4, 192>>>(W_out, b_out);
    viterbi_kernel<<<1, 32, vit_smem>>>(transitions, out, out_size);
}

// round 17
// speedup vs baseline: 1.2067x; 1.0066x over previous
#include <cuda_runtime.h>
#include <math.h>

#define T_LEN 2048
#define BATCH 64
#define EMB   100
#define HID   128
#define G3    384   // 3*HID gate rows
#define NS    6     // CRF states

#define KNEG (-1.44269504088896340736f)   // -log2(e)

// ---------------- device scratch (no allocation allowed) ----------------
// g_gi padded by 1 timestep each side -> branchless prefetch in the GRU loop
// r,z rows: -log2e * (x@Wih^T + bih + bhh); n rows: plain x@Wih^T + bih
__device__ float g_gi[2][T_LEN + 2][G3];
__device__ float g_hout[2][T_LEN][HID];
__device__ __align__(16) float g_logits[T_LEN * NS];

// ---------------- f32x2 helpers (packed dual-FP32 FMA, sm_100+) ---------
__device__ __forceinline__ unsigned long long ffma2(unsigned long long a,
                                                    unsigned long long b,
                                                    unsigned long long c) {
    unsigned long long d;
    asm("fma.rn.f32x2 %0, %1, %2, %3;" : "=l"(d) : "l"(a), "l"(b), "l"(c));
    return d;
}
__device__ __forceinline__ unsigned long long fadd2(unsigned long long a,
                                                    unsigned long long b) {
    unsigned long long d;
    asm("add.rn.f32x2 %0, %1, %2;" : "=l"(d) : "l"(a), "l"(b));
    return d;
}
__device__ __forceinline__ unsigned long long pack2(float lo, float hi) {
    unsigned long long d;
    asm("mov.b64 %0, {%1, %2};" : "=l"(d) : "f"(lo), "f"(hi));
    return d;
}
__device__ __forceinline__ float2 unpack2(unsigned long long u) {
    float2 r;
    asm("mov.b64 {%0, %1}, %2;" : "=f"(r.x), "=f"(r.y) : "l"(u));
    return r;
}
__device__ __forceinline__ float fex2(float x) {
    float r; asm("ex2.approx.f32 %0, %1;" : "=f"(r) : "f"(x)); return r;
}
__device__ __forceinline__ float frcp(float x) {
    float r; asm("rcp.approx.f32 %0, %1;" : "=f"(r) : "f"(x)); return r;
}
__device__ __forceinline__ float ftanh(float x) {
    float r; asm("tanh.approx.f32 %0, %1;" : "=f"(r) : "f"(x)); return r;
}

// ================= Kernel 1: gi precompute (16 timesteps per block) =======
// r,z rows: -log2e*(x@Wih^T + bih + bhh);  n rows: x@Wih^T + bih (plain)
__global__ void __launch_bounds__(G3) gi_kernel(
    const int* __restrict__ sentence, const float* __restrict__ emb,
    const float* __restrict__ Wf_ih, const float* __restrict__ bf_ih,
    const float* __restrict__ Wb_ih, const float* __restrict__ bb_ih,
    const float* __restrict__ bf_hh, const float* __restrict__ bb_hh)
{
    const int dir = blockIdx.y;
    const int t0  = blockIdx.x * 16;
    __shared__ float x_s[16][EMB];

    for (int i = threadIdx.x; i < 16 * EMB; i += G3) {
        int tt = i / EMB, e = i % EMB;
        int tok = sentence[63 * T_LEN + t0 + tt];
        x_s[tt][e] = emb[tok * EMB + e];
    }
    __syncthreads();

    const float* W   = dir ? Wb_ih : Wf_ih;
    const float* b   = dir ? bb_ih : bf_ih;
    const float* bhh = dir ? bb_hh : bf_hh;
    const int j = threadIdx.x;

    float bj = b[j] + ((j < 2 * HID) ? bhh[j] : 0.0f);
    const float scale = (j < 2 * HID) ? KNEG : 1.0f;
    float acc[16];
#pragma unroll
    for (int q = 0; q < 16; q++) acc[q] = bj;
    const float* Wr = W + j * EMB;
#pragma unroll
    for (int e = 0; e < EMB; e++) {
        float w = __ldg(Wr + e);
#pragma unroll
        for (int q = 0; q < 16; q++) acc[q] += w * x_s[q][e];
    }
#pragma unroll
    for (int q = 0; q < 16; q++) g_gi[dir][t0 + q + 1][j] = acc[q] * scale;
}

// ================= Kernel 2: GRU recurrence (round-10/13 proven) ==========
// grid 2, block 256. Thread pair (2u,2u+1) owns unit u; r,z,n half-dots over
// its 64-slice of h, shfl_xor(1) combine, thread-local tail, ONE barrier.
// n gate via single MUFU.TANH.  FROZEN — do not touch live state.
__global__ void __launch_bounds__(256, 1) gru_kernel(
    const float* __restrict__ Wf_hh, const float* __restrict__ bf_hh,
    const float* __restrict__ Wb_hh, const float* __restrict__ bb_hh,
    const float* __restrict__ h0)
{
    const int dir  = blockIdx.x;
    const int tid  = threadIdx.x;
    const int unit = tid >> 1;       // 0..127
    const int half = tid & 1;        // which 64-slice of h

    __shared__ __align__(16) float h_s[2][136];

    const float* Whh = dir ? Wb_hh : Wf_hh;
    const float* bhh = dir ? bb_hh : bf_hh;

    unsigned long long wr[32], wz[32], wn[32];
    {
        const unsigned long long* Pr = reinterpret_cast<const unsigned long long*>(
            Whh + unit * HID + half * 64);
        const unsigned long long* Pz = reinterpret_cast<const unsigned long long*>(
            Whh + (HID + unit) * HID + half * 64);
        const unsigned long long* Pn = reinterpret_cast<const unsigned long long*>(
            Whh + (2 * HID + unit) * HID + half * 64);
#pragma unroll
        for (int k = 0; k < 32; k++) {
            wr[k] = __ldg(Pr + k);
            wz[k] = __ldg(Pz + k);
            wn[k] = __ldg(Pn + k);
        }
    }
    const float bias_n = bhh[2 * HID + unit];
    const unsigned long long an_init =
        (half == 0) ? pack2(bias_n, 0.0f) : 0ull;

    float hold = h0[dir * (BATCH * HID) + 63 * HID + unit];
    const int wslot = unit + ((unit >> 6) << 3);
    if (half == 0) h_s[0][wslot] = hold;
    __syncthreads();

    const int tstep = dir ? -1 : 1;
    int t0q = dir ? (T_LEN - 1) : 0;
    const float* gip  = &g_gi[dir][1][0] + t0q * G3 + unit;
    float*       houp = &g_hout[dir][0][0] + t0q * HID + unit;
    const int gstep = tstep * G3;
    const int hstep = tstep * HID;

    float gr = __ldg(gip);              // -log2e prescaled
    float gz = __ldg(gip + HID);        // -log2e prescaled
    float gn = __ldg(gip + 2 * HID);    // plain
    gip += gstep;

    const int hoff = half ? 72 : 0;

#pragma unroll 4
    for (int s = 0; s < T_LEN; s++) {
        const int p = s & 1;
        float gr2 = __ldg(gip);
        float gz2 = __ldg(gip + HID);
        float gn2 = __ldg(gip + 2 * HID);
        gip += gstep;

        unsigned long long ar0 = 0ull, ar1 = 0ull;
        unsigned long long az0 = 0ull, az1 = 0ull;
        unsigned long long an0 = an_init, an1 = 0ull;
        const ulonglong2* h2 =
            reinterpret_cast<const ulonglong2*>(&h_s[p][hoff]);
#pragma unroll
        for (int q = 0; q < 16; q++) {
            ulonglong2 v = h2[q];
            ar0 = ffma2(wr[2 * q], v.x, ar0);
            ar1 = ffma2(wr[2 * q + 1], v.y, ar1);
            az0 = ffma2(wz[2 * q], v.x, az0);
            az1 = ffma2(wz[2 * q + 1], v.y, az1);
            an0 = ffma2(wn[2 * q], v.x, an0);
            an1 = ffma2(wn[2 * q + 1], v.y, an1);
        }
        // r drains first: sr chain hides under z/n drains
        float2 fr = unpack2(fadd2(ar0, ar1));
        float pr = fr.x + fr.y;
        float dr = pr + __shfl_xor_sync(0xFFFFFFFFu, pr, 1);
        float2 fz = unpack2(fadd2(az0, az1));
        float pz = fz.x + fz.y;
        float dz = pz + __shfl_xor_sync(0xFFFFFFFFu, pz, 1);
        float2 fn = unpack2(fadd2(an0, an1));
        float pn = fn.x + fn.y;
        float dn = pn + __shfl_xor_sync(0xFFFFFFFFu, pn, 1);

        float sr = frcp(1.0f + fex2(fmaf(KNEG, dr, gr)));   // sigmoid
        float sz = frcp(1.0f + fex2(fmaf(KNEG, dz, gz)));   // sigmoid
        float nn = ftanh(fmaf(sr, dn, gn));                 // MUFU.TANH
        float hnew = fmaf(sz, hold - nn, nn);               // (1-z)n + z h

        if (half == 0) h_s[p ^ 1][wslot] = hnew;            // publish
        else           *houp = hnew;                        // stream out
        __syncthreads();                                    // only barrier

        hold = hnew;
        gr = gr2; gz = gz2; gn = gn2;
        houp += hstep;
    }
}

// ============ Kernel 3: output projection + softmax, 8 t per block ========
__global__ void __launch_bounds__(192) proj_kernel(
    const float* __restrict__ W_out, const float* __restrict__ b_out)
{
    const int wid  = threadIdx.x >> 5;   // state 0..5
    const int lane = threadIdx.x & 31;
    __shared__ float lg_s[NS];

    const float* Wr = W_out + wid * (2 * HID);

#pragma unroll
    for (int q = 0; q < 8; q++) {
        const int t = blockIdx.x * 8 + q;

        float acc = 0.0f;
#pragma unroll
        for (int i = lane; i < 2 * HID; i += 32) {
            float c = (i < HID) ? g_hout[0][t][i] : g_hout[1][t][i - HID];
            acc += c * __ldg(Wr + i);
        }
#pragma unroll
        for (int off = 16; off; off >>= 1)
            acc += __shfl_xor_sync(0xFFFFFFFFu, acc, off);
        if (lane == 0) lg_s[wid] = acc + b_out[wid];
        __syncthreads();

        if (threadIdx.x == 0) {
            float m = lg_s[0];
#pragma unroll
            for (int i = 1; i < NS; i++) m = fmaxf(m, lg_s[i]);
            float e[NS];
            float sum = 0.0f;
#pragma unroll
            for (int i = 0; i < NS; i++) { e[i] = expf(lg_s[i] - m); sum += e[i]; }
            float inv = 1.0f / sum;
#pragma unroll
            for (int i = 0; i < NS; i++) g_logits[t * NS + i] = e[i] * inv;
        }
        __syncthreads();
    }
}

// ================= Kernel 4: Viterbi (1 warp) — round-5 proven, FROZEN ====
__global__ void viterbi_kernel(const float* __restrict__ transitions,
                               float* __restrict__ out, int out_size)
{
    extern __shared__ char sm[];
    float*         lg_sh = (float*)sm;                        // T*6 floats
    unsigned char* bp8   = (unsigned char*)(sm + T_LEN * NS * 4); // (T-1)*8
    const int lane = threadIdx.x;

    {   // stage logits into SMEM
        const float4* src = (const float4*)g_logits;
        float4*       dst = (float4*)lg_sh;
        for (int i = lane; i < T_LEN * NS / 4; i += 32) dst[i] = src[i];
    }
    __syncwarp();

    float Tc[NS];
#pragma unroll
    for (int i = 0; i < NS; i++)
        Tc[i] = (lane < NS) ? transitions[i * NS + lane] : 0.0f;

    const int l6 = (lane < NS) ? lane : 0;
    float tr = (lane < NS) ? lg_sh[lane] : -1e30f;

    for (int t = 1; t < T_LEN; t++) {
        float lgv = lg_sh[t * NS + l6];
        float v0 = __shfl_sync(0xFFFFFFFFu, tr, 0) + Tc[0];
        float v1 = __shfl_sync(0xFFFFFFFFu, tr, 1) + Tc[1];
        float v2 = __shfl_sync(0xFFFFFFFFu, tr, 2) + Tc[2];
        float v3 = __shfl_sync(0xFFFFFFFFu, tr, 3) + Tc[3];
        float v4 = __shfl_sync(0xFFFFFFFFu, tr, 4) + Tc[4];
        float v5 = __shfl_sync(0xFFFFFFFFu, tr, 5) + Tc[5];
        float m01 = fmaxf(v0, v1);  int i01 = (v0 >= v1) ? 0 : 1;
        float m23 = fmaxf(v2, v3);  int i23 = (v2 >= v3) ? 2 : 3;
        float m45 = fmaxf(v4, v5);  int i45 = (v4 >= v5) ? 4 : 5;
        float m03 = fmaxf(m01, m23); int i03 = (m01 >= m23) ? i01 : i23;
        float m   = fmaxf(m03, m45); int bi  = (m03 >= m45) ? i03 : i45;
        if (lane < NS) {
            tr = lgv + m;
            bp8[(t - 1) * 8 + lane] = (unsigned char)bi;
        }
    }

    float f0 = __shfl_sync(0xFFFFFFFFu, tr, 0);
    float f1 = __shfl_sync(0xFFFFFFFFu, tr, 1);
    float f2 = __shfl_sync(0xFFFFFFFFu, tr, 2);
    float f3 = __shfl_sync(0xFFFFFFFFu, tr, 3);
    float f4 = __shfl_sync(0xFFFFFFFFu, tr, 4);
    float f5 = __shfl_sync(0xFFFFFFFFu, tr, 5);
    float n01 = fmaxf(f0, f1);  int k01 = (f0 >= f1) ? 0 : 1;
    float n23 = fmaxf(f2, f3);  int k23 = (f2 >= f3) ? 2 : 3;
    float n45 = fmaxf(f4, f5);  int k45 = (f4 >= f5) ? 4 : 5;
    float n03 = fmaxf(n01, n23); int k03 = (n01 >= n23) ? k01 : k23;
    float score = fmaxf(n03, n45); int last = (n03 >= n45) ? k03 : k45;
    if (lane == 0) out[0] = score;
    __syncwarp();

    // ---- parallel backtrack: 32 chunks x 64 steps, nibble maps ----
    const unsigned int IDENT = 0x00543210u;
    unsigned int mp_loc[64];
#pragma unroll
    for (int s2 = 0; s2 < 64; s2++) {
        int k = lane * 64 + s2;
        if (k <= T_LEN - 2) {
            unsigned long long f8 =
                *reinterpret_cast<const unsigned long long*>(&bp8[k * 8]);
            unsigned int lo = (unsigned int)f8;
            unsigned int hi = (unsigned int)(f8 >> 32);
            mp_loc[s2] = (lo & 0xFu) | ((lo >> 4) & 0xF0u) |
                         ((lo >> 8) & 0xF00u) | ((lo >> 12) & 0xF000u) |
                         ((hi & 0xFu) << 16) | (((hi >> 8) & 0xFu) << 20);
        } else {
            mp_loc[s2] = IDENT;
        }
    }
    unsigned int M = IDENT;
#pragma unroll
    for (int s2 = 63; s2 >= 0; s2--) {
        unsigned int f = mp_loc[s2];
        unsigned int Mn = 0;
#pragma unroll
        for (int jq = 0; jq < 6; jq++) {
            unsigned int y = (M >> (4 * jq)) & 15u;
            Mn |= ((f >> (4 * y)) & 15u) << (4 * jq);
        }
        M = Mn;
    }
    unsigned int S = M;
#pragma unroll
    for (int d = 1; d < 32; d <<= 1) {
        unsigned int other = __shfl_down_sync(0xFFFFFFFFu, S, d);
        if (lane + d < 32) {
            unsigned int Sn = 0;
#pragma unroll
            for (int jq = 0; jq < 6; jq++) {
                unsigned int y = (other >> (4 * jq)) & 15u;
                Sn |= ((S >> (4 * y)) & 15u) << (4 * jq);
            }
            S = Sn;
        }
    }
    unsigned int Snext = __shfl_down_sync(0xFFFFFFFFu, S, 1);
    int cur = (lane == 31) ? last : (int)((Snext >> (4 * last)) & 15u);
#pragma unroll
    for (int s2 = 63; s2 >= 0; s2--) {
        int k = lane * 64 + s2;
        if (k <= T_LEN - 2) {
            cur = (int)((mp_loc[s2] >> (4 * cur)) & 15u);
            out[1 + k] = (float)cur;
        }
    }
    if (lane == 31) out[1 + T_LEN - 1] = (float)last;
    for (int i = T_LEN + 1 + lane; i < out_size; i += 32) out[i] = 0.0f;
}

// ============================ launch =======================================
extern "C" void kernel_launch(void* const* d_in, const int* in_sizes, int n_in,
                              void* d_out, int out_size) {
    const int*   sentence    = (const int*)d_in[0];
    const float* emb         = (const float*)d_in[1];
    const float* h0          = (const float*)d_in[2];
    const float* Wf_ih       = (const float*)d_in[3];
    const float* Wf_hh       = (const float*)d_in[4];
    const float* bf_ih       = (const float*)d_in[5];
    const float* bf_hh       = (const float*)d_in[6];
    const float* Wb_ih       = (const float*)d_in[7];
    const float* Wb_hh       = (const float*)d_in[8];
    const float* bb_ih       = (const float*)d_in[9];
    const float* bb_hh       = (const float*)d_in[10];
    const float* W_out       = (const float*)d_in[11];
    const float* b_out       = (const float*)d_in[12];
    const float* transitions = (const float*)d_in[13];
    float*       out         = (float*)d_out;

    const int vit_smem = T_LEN * NS * 4 + (T_LEN - 1) * 8;  // 65528 B
    cudaFuncSetAttribute(viterbi_kernel,
                         cudaFuncAttributeMaxDynamicSharedMemorySize, vit_smem);

    gi_kernel<<<dim3(T_LEN / 16, 2), G3>>>(sentence, emb, Wf_ih, bf_ih,
                                           Wb_ih, bb_ih, bf_hh, bb_hh);
    gru_kernel<<<2, 256>>>(Wf_hh, bf_hh, Wb_hh, bb_hh, h0);
    proj_kernel<<<T_LEN / 8, 192>>>(W_out, b_out);
    viterbi_kernel<<<1, 32, vit_smem>>>(transitions, out, out_size);
}